// round 2
// baseline (speedup 1.0000x reference)
#include <cuda_runtime.h>

// Device-global scratch (no allocations allowed).
__device__ unsigned long long g_mismatch_count;

__global__ void zero_counter_kernel() {
    g_mismatch_count = 0ULL;
}

__device__ __forceinline__ int group_of(int c) {
    // classes 0..2 -> 0, 3..5 -> 1, 6..7 -> 2
    return (c < 3) ? 0 : ((c < 6) ? 1 : 2);
}

__global__ void __launch_bounds__(256) path_loss_reduce_kernel(
    const float4* __restrict__ preds,   // [batch * 2] float4 (8 floats per row)
    const int* __restrict__ targets,    // [batch] int32 (JAX x64-disabled demotes int64)
    int batch)
{
    int idx = blockIdx.x * blockDim.x + threadIdx.x;
    int stride = gridDim.x * blockDim.x;

    unsigned int local = 0;

    for (int i = idx; i < batch; i += stride) {
        float4 a = preds[2 * i];
        float4 b = preds[2 * i + 1];
        int t = targets[i];

        // argmax of 8 with first-max tie-break (strict >)
        float m = a.x; int am = 0;
        if (a.y > m) { m = a.y; am = 1; }
        if (a.z > m) { m = a.z; am = 2; }
        if (a.w > m) { m = a.w; am = 3; }
        if (b.x > m) { m = b.x; am = 4; }
        if (b.y > m) { m = b.y; am = 5; }
        if (b.z > m) { m = b.z; am = 6; }
        if (b.w > m) { m = b.w; am = 7; }

        int pg = group_of(am);
        int tg = group_of(t);
        local += (pg != tg) ? 1u : 0u;
    }

    // warp reduction
    #pragma unroll
    for (int off = 16; off > 0; off >>= 1)
        local += __shfl_down_sync(0xFFFFFFFFu, local, off);

    __shared__ unsigned int warp_sums[8];
    int lane = threadIdx.x & 31;
    int wid = threadIdx.x >> 5;
    if (lane == 0) warp_sums[wid] = local;
    __syncthreads();

    if (wid == 0) {
        unsigned int v = (lane < (blockDim.x >> 5)) ? warp_sums[lane] : 0u;
        #pragma unroll
        for (int off = 4; off > 0; off >>= 1)
            v += __shfl_down_sync(0xFFFFFFFFu, v, off);
        if (lane == 0)
            atomicAdd(&g_mismatch_count, (unsigned long long)v);
    }
}

__global__ void finalize_kernel(float* out, int batch) {
    *out = (float)((double)g_mismatch_count / (double)batch);
}

extern "C" void kernel_launch(void* const* d_in, const int* in_sizes, int n_in,
                              void* d_out, int out_size) {
    const float4* preds = (const float4*)d_in[0];   // [B, 8] f32
    const int* targets = (const int*)d_in[1];       // [B] int32
    int batch = in_sizes[0] / 8;                    // derive from predictions, robust
    float* out = (float*)d_out;

    zero_counter_kernel<<<1, 1>>>();

    const int threads = 256;
    // 4096 blocks x 256 threads -> 1M threads, ~4 rows each at B = 4.19M.
    int blocks = 4096;
    path_loss_reduce_kernel<<<blocks, threads>>>(preds, targets, batch);

    finalize_kernel<<<1, 1>>>(out, batch);
}